// round 2
// baseline (speedup 1.0000x reference)
#include <cuda_runtime.h>

// Problem constants (fixed by the reference)
#define NN 50000
#define EE 800000
#define HH 64
#define GG 256

// ---------------- scratch (device globals; no runtime allocation) ----------
__device__ float g_q[NN * HH];
__device__ float g_k[NN * HH];
__device__ float g_v[NN * HH];
__device__ float g_s[NN * HH];   // skip = in @ Ws + bs
__device__ float g_h[NN * HH];   // layer output (reused for both layers)

__device__ int   g_cnt[NN];      // per-dst edge counts
__device__ int   g_off[NN + 1];  // CSR row offsets
__device__ int   g_cur[NN];      // scatter cursors
__device__ int   g_csrc[EE];     // CSR: src node per edge slot
__device__ float g_cw[EE];       // CSR: edge weight per edge slot

__device__ float g_pool[GG * HH];
__device__ float g_pcnt[GG];

// ---------------- zero scratch ---------------------------------------------
__global__ void zero_kernel() {
    int i = blockIdx.x * blockDim.x + threadIdx.x;
    const int total = NN + NN + GG * HH + GG;
    for (; i < total; i += gridDim.x * blockDim.x) {
        if (i < NN)                 g_cnt[i] = 0;
        else if (i < 2 * NN)        g_cur[i - NN] = 0;
        else if (i < 2 * NN + GG * HH) g_pool[i - 2 * NN] = 0.f;
        else                        g_pcnt[i - 2 * NN - GG * HH] = 0.f;
    }
}

// ---------------- CSR build -------------------------------------------------
__global__ void count_kernel(const int* __restrict__ ei) {
    int e = blockIdx.x * blockDim.x + threadIdx.x;
    if (e < EE) {
        int dst = ei[EE + e];
        atomicAdd(&g_cnt[dst], 1);
    }
}

// Single-block exclusive scan over 50000 counts.
__global__ void scan_kernel() {
    __shared__ int part[1024];
    const int t = threadIdx.x;
    const int CH = 49;  // 1024 * 49 = 50176 >= NN
    int start = t * CH;
    int sum = 0;
    for (int i = start; i < start + CH && i < NN; i++) sum += g_cnt[i];
    part[t] = sum;
    __syncthreads();
    // Hillis-Steele inclusive scan
    for (int off = 1; off < 1024; off <<= 1) {
        int v = (t >= off) ? part[t - off] : 0;
        __syncthreads();
        part[t] += v;
        __syncthreads();
    }
    int run = (t == 0) ? 0 : part[t - 1];
    for (int i = start; i < start + CH && i < NN; i++) {
        g_off[i] = run;
        run += g_cnt[i];
    }
    if (t == 1023) g_off[NN] = part[1023];
}

__global__ void scatter_kernel(const int* __restrict__ ei,
                               const float* __restrict__ ew) {
    int e = blockIdx.x * blockDim.x + threadIdx.x;
    if (e < EE) {
        int src = ei[e];
        int dst = ei[EE + e];
        int pos = g_off[dst] + atomicAdd(&g_cur[dst], 1);
        g_csrc[pos] = src;
        g_cw[pos]   = ew[e];
    }
}

// ---------------- fused 2-matrix GEMM: out{A,B}[n] = in[n] @ W{A,B} + b ----
// Block: 256 threads, 32 nodes/block. Each thread: 1 node x 16 feats of 1 mat.
__global__ __launch_bounds__(256) void gemm2_kernel(
    const float* __restrict__ xin, int use_h, int vs,
    const float* __restrict__ WA, const float* __restrict__ bA,
    const float* __restrict__ WB, const float* __restrict__ bB) {
    __shared__ float xs[32][65];
    __shared__ float Wsh[2][64][64];

    const float* in = use_h ? g_h : xin;
    float* outA = vs ? g_v : g_q;
    float* outB = vs ? g_s : g_k;

    const int t  = threadIdx.x;
    const int n0 = blockIdx.x * 32;

    for (int i = t; i < 8192; i += 256)
        ((float*)Wsh)[i] = (i < 4096) ? WA[i] : WB[i - 4096];
    for (int i = t; i < 2048; i += 256) {
        int nl = i >> 6, kk = i & 63;
        int n = n0 + nl;
        xs[nl][kk] = (n < NN) ? in[n * 64 + kk] : 0.f;
    }
    __syncthreads();

    const int nl  = t >> 3;
    const int u   = t & 7;
    const int mat = u >> 2;
    const int f0  = (u & 3) * 16;

    float acc[16];
#pragma unroll
    for (int j = 0; j < 16; j++) acc[j] = 0.f;

#pragma unroll 4
    for (int kk = 0; kk < 64; kk++) {
        float xv = xs[nl][kk];
        const float4* w4 = (const float4*)&Wsh[mat][kk][f0];
#pragma unroll
        for (int jj = 0; jj < 4; jj++) {
            float4 w = w4[jj];
            acc[jj * 4 + 0] += xv * w.x;
            acc[jj * 4 + 1] += xv * w.y;
            acc[jj * 4 + 2] += xv * w.z;
            acc[jj * 4 + 3] += xv * w.w;
        }
    }

    int n = n0 + nl;
    if (n < NN) {
        float* op       = mat ? outB : outA;
        const float* bp = mat ? bB : bA;
#pragma unroll
        for (int j = 0; j < 16; j++)
            op[n * 64 + f0 + j] = acc[j] + bp[f0 + j];
    }
}

// ---------------- edge aggregation: warp per dst, online softmax -----------
__global__ __launch_bounds__(256) void edge_agg_kernel(const float* __restrict__ We) {
    int wid  = (blockIdx.x * blockDim.x + threadIdx.x) >> 5;
    int lane = threadIdx.x & 31;
    if (wid >= NN) return;
    const int dst = wid;

    const int i0 = g_off[dst], i1 = g_off[dst + 1];
    const float2 qv = *(const float2*)&g_q[dst * 64 + lane * 2];
    const float2 we = *(const float2*)&We[lane * 2];

    float m = -1e30f, s = 0.f, a0 = 0.f, a1 = 0.f;
    for (int i = i0; i < i1; i++) {
        int   src = g_csrc[i];
        float w   = g_cw[i];
        float e0 = w * we.x, e1 = w * we.y;
        const float2 kk = *(const float2*)&g_k[src * 64 + lane * 2];
        const float2 vv = *(const float2*)&g_v[src * 64 + lane * 2];
        float k0 = kk.x + e0, k1 = kk.y + e1;
        float v0 = vv.x + e0, v1 = vv.y + e1;

        float p = qv.x * k0 + qv.y * k1;
#pragma unroll
        for (int off = 16; off; off >>= 1)
            p += __shfl_xor_sync(0xffffffffu, p, off);
        float logit = p * 0.125f;  // 1/sqrt(64)

        float nm = fmaxf(m, logit);
        float sc = __expf(m - nm);
        float pe = __expf(logit - nm);
        s  = s * sc + pe;
        a0 = a0 * sc + pe * v0;
        a1 = a1 * sc + pe * v1;
        m  = nm;
    }

    float inv = 1.f / (s + 1e-16f);
    const float2 sk = *(const float2*)&g_s[dst * 64 + lane * 2];
    float2 o;
    o.x = fmaxf(a0 * inv + sk.x, 0.f);
    o.y = fmaxf(a1 * inv + sk.y, 0.f);
    *(float2*)&g_h[dst * 64 + lane * 2] = o;
}

// ---------------- mean pool by graph ---------------------------------------
__global__ __launch_bounds__(256) void pool_kernel(const int* __restrict__ batch) {
    int wid  = (blockIdx.x * blockDim.x + threadIdx.x) >> 5;
    int lane = threadIdx.x & 31;
    if (wid >= NN) return;
    int g = batch[wid];
    float2 hv = *(const float2*)&g_h[wid * 64 + lane * 2];
    atomicAdd(&g_pool[g * 64 + lane * 2], hv.x);
    atomicAdd(&g_pool[g * 64 + lane * 2 + 1], hv.y);
    if (lane == 0) atomicAdd(&g_pcnt[g], 1.f);
}

// ---------------- classifier head ------------------------------------------
__global__ void final_kernel(const float* __restrict__ Wl,
                             const float* __restrict__ bl,
                             float* __restrict__ out) {
    int t = threadIdx.x;  // 512 = GG * 2
    int g = t >> 1, c = t & 1;
    float cnt = fmaxf(g_pcnt[g], 1.f);
    float sum = 0.f;
    for (int f = 0; f < 64; f++)
        sum += g_pool[g * 64 + f] * Wl[f * 2 + c];
    out[g * 2 + c] = sum / cnt + bl[c];
}

// ---------------- launch ----------------------------------------------------
extern "C" void kernel_launch(void* const* d_in, const int* in_sizes, int n_in,
                              void* d_out, int out_size) {
    const float* x     = (const float*)d_in[0];
    const int*   ei    = (const int*)d_in[1];    // int32: JAX x64-disabled downcasts int64
    const float* ew    = (const float*)d_in[2];
    const int*   batch = (const int*)d_in[3];
    const float *Wq1 = (const float*)d_in[4],  *bq1 = (const float*)d_in[5];
    const float *Wk1 = (const float*)d_in[6],  *bk1 = (const float*)d_in[7];
    const float *Wv1 = (const float*)d_in[8],  *bv1 = (const float*)d_in[9];
    const float *We1 = (const float*)d_in[10];
    const float *Ws1 = (const float*)d_in[11], *bs1 = (const float*)d_in[12];
    const float *Wq2 = (const float*)d_in[13], *bq2 = (const float*)d_in[14];
    const float *Wk2 = (const float*)d_in[15], *bk2 = (const float*)d_in[16];
    const float *Wv2 = (const float*)d_in[17], *bv2 = (const float*)d_in[18];
    const float *We2 = (const float*)d_in[19];
    const float *Ws2 = (const float*)d_in[20], *bs2 = (const float*)d_in[21];
    const float *Wl  = (const float*)d_in[22], *bl  = (const float*)d_in[23];
    float* out = (float*)d_out;

    const int GEMM_BLOCKS = (NN + 31) / 32;           // 1563
    const int EDGE_BLOCKS = (EE + 255) / 256;         // 3125
    const int WARP_BLOCKS = (NN * 32 + 255) / 256;    // 6250

    // CSR build (shared by both layers) + scratch zeroing
    zero_kernel<<<456, 256>>>();
    count_kernel<<<EDGE_BLOCKS, 256>>>(ei);
    scan_kernel<<<1, 1024>>>();
    scatter_kernel<<<EDGE_BLOCKS, 256>>>(ei, ew);

    // Layer 1
    gemm2_kernel<<<GEMM_BLOCKS, 256>>>(x, 0, 0, Wq1, bq1, Wk1, bk1);
    gemm2_kernel<<<GEMM_BLOCKS, 256>>>(x, 0, 1, Wv1, bv1, Ws1, bs1);
    edge_agg_kernel<<<WARP_BLOCKS, 256>>>(We1);

    // Layer 2 (input = g_h, output overwrites g_h)
    gemm2_kernel<<<GEMM_BLOCKS, 256>>>(x, 1, 0, Wq2, bq2, Wk2, bk2);
    gemm2_kernel<<<GEMM_BLOCKS, 256>>>(x, 1, 1, Wv2, bv2, Ws2, bs2);
    edge_agg_kernel<<<WARP_BLOCKS, 256>>>(We2);

    // Pool + head
    pool_kernel<<<WARP_BLOCKS, 256>>>(batch);
    final_kernel<<<1, 512>>>(Wl, bl, out);
}

// round 3
// speedup vs baseline: 3.1289x; 3.1289x over previous
#include <cuda_runtime.h>

// Problem constants (fixed by the reference)
#define NN 50000
#define EE 800000
#define HH 64
#define GG 256

#define SCAN_T 1024
#define SCAN_CH 52                      // 13 int4 per thread
#define CNT_PAD (SCAN_T * SCAN_CH)      // 53248

// ---------------- scratch (device globals; no runtime allocation) ----------
__device__ float g_q[NN * HH];
__device__ float g_k[NN * HH];
__device__ float g_v[NN * HH];
__device__ float g_s[NN * HH];   // skip = in @ Ws + bs
__device__ float g_h[NN * HH];   // layer-1 output

__device__ int   g_cnt[CNT_PAD];     // per-dst edge counts (padded)
__device__ int   g_off[CNT_PAD + 4]; // CSR row offsets (padded for int4 tail)
__device__ int   g_cur[NN];          // scatter cursors
__device__ int   g_csrc[EE];         // CSR: src node per edge slot
__device__ float g_cw[EE];           // CSR: edge weight per edge slot

__device__ float g_pool[GG * HH];
__device__ float g_pcnt[GG];

// ---------------- zero scratch ---------------------------------------------
__global__ void zero_kernel() {
    int i = blockIdx.x * blockDim.x + threadIdx.x;
    const int T1 = CNT_PAD;                 // g_cnt
    const int T2 = T1 + NN;                 // g_cur
    const int T3 = T2 + GG * HH;            // g_pool
    const int T4 = T3 + GG;                 // g_pcnt
    for (; i < T4; i += gridDim.x * blockDim.x) {
        if (i < T1)      g_cnt[i] = 0;
        else if (i < T2) g_cur[i - T1] = 0;
        else if (i < T3) g_pool[i - T2] = 0.f;
        else             g_pcnt[i - T3] = 0.f;
    }
}

// ---------------- CSR counts + graph node counts (int4 loads) --------------
__global__ void count_kernel(const int* __restrict__ ei,
                             const int* __restrict__ batch) {
    int t = blockIdx.x * blockDim.x + threadIdx.x;
    const int NE4 = EE / 4;       // 200000
    const int NB4 = NN / 4;       // 12500
    if (t < NE4) {
        int4 d = ((const int4*)(ei + EE))[t];
        atomicAdd(&g_cnt[d.x], 1);
        atomicAdd(&g_cnt[d.y], 1);
        atomicAdd(&g_cnt[d.z], 1);
        atomicAdd(&g_cnt[d.w], 1);
    } else if (t < NE4 + NB4) {
        int4 b = ((const int4*)batch)[t - NE4];
        atomicAdd(&g_pcnt[b.x], 1.f);
        atomicAdd(&g_pcnt[b.y], 1.f);
        atomicAdd(&g_pcnt[b.z], 1.f);
        atomicAdd(&g_pcnt[b.w], 1.f);
    }
}

// ---------------- single-block exclusive scan (vectorized) ------------------
__global__ void scan_kernel() {
    __shared__ int part[SCAN_T];
    const int t = threadIdx.x;
    const int base4 = t * (SCAN_CH / 4);          // 13 int4 per thread
    const int4* c4 = (const int4*)g_cnt;

    int sum = 0;
#pragma unroll
    for (int c = 0; c < SCAN_CH / 4; c++) {
        int4 v = c4[base4 + c];
        sum += v.x + v.y + v.z + v.w;
    }
    part[t] = sum;
    __syncthreads();
    for (int off = 1; off < SCAN_T; off <<= 1) {
        int v = (t >= off) ? part[t - off] : 0;
        __syncthreads();
        part[t] += v;
        __syncthreads();
    }
    int run = (t == 0) ? 0 : part[t - 1];
    int4* o4 = (int4*)g_off;
#pragma unroll
    for (int c = 0; c < SCAN_CH / 4; c++) {
        int4 v = c4[base4 + c];
        int4 o;
        o.x = run; run += v.x;
        o.y = run; run += v.y;
        o.z = run; run += v.z;
        o.w = run; run += v.w;
        o4[base4 + c] = o;
    }
    if (t == SCAN_T - 1) g_off[CNT_PAD] = run;   // total; g_off[NN] already == prefix
}

// ---------------- scatter into CSR (int4/float4 loads) ----------------------
__global__ void scatter_kernel(const int* __restrict__ ei,
                               const float* __restrict__ ew) {
    int t = blockIdx.x * blockDim.x + threadIdx.x;
    if (t >= EE / 4) return;
    int4   s4 = ((const int4*)ei)[t];
    int4   d4 = ((const int4*)(ei + EE))[t];
    float4 w4 = ((const float4*)ew)[t];
    int p;
    p = g_off[d4.x] + atomicAdd(&g_cur[d4.x], 1); g_csrc[p] = s4.x; g_cw[p] = w4.x;
    p = g_off[d4.y] + atomicAdd(&g_cur[d4.y], 1); g_csrc[p] = s4.y; g_cw[p] = w4.y;
    p = g_off[d4.z] + atomicAdd(&g_cur[d4.z], 1); g_csrc[p] = s4.z; g_cw[p] = w4.z;
    p = g_off[d4.w] + atomicAdd(&g_cur[d4.w], 1); g_csrc[p] = s4.w; g_cw[p] = w4.w;
}

// ---------------- fused 4-matrix GEMM --------------------------------------
// out{q,k,v,s}[n] = in[n] @ W{q,k,v,s} + b.  Tile: 64 nodes x 256 feats.
// 256 threads; thread = 8 nodes x (4 feats in q|k region + 4 feats in v|s region).
#define GEMM_SMEM (64 * 256 * 4 + 64 * 68 * 4)   // 82944 bytes

__global__ __launch_bounds__(256, 2) void gemm4_kernel(
    const float* __restrict__ xin, int use_h,
    const float* __restrict__ Wq, const float* __restrict__ bq,
    const float* __restrict__ Wk, const float* __restrict__ bk,
    const float* __restrict__ Wv, const float* __restrict__ bv,
    const float* __restrict__ Ws, const float* __restrict__ bs) {
    extern __shared__ float smem[];
    float* Wsh = smem;              // [64][256]
    float* xst = smem + 64 * 256;   // [64][68]  (transposed x tile, padded)

    const float* in = use_h ? g_h : xin;
    const int t  = threadIdx.x;
    const int n0g = blockIdx.x * 64;

    // Load weights: Wsh[kk][mat*64 + f]
    for (int i = t; i < 4096; i += 256) {
        int kk = i >> 6, f = i & 63;
        float* row = &Wsh[kk * 256];
        row[f]       = Wq[i];
        row[64 + f]  = Wk[i];
        row[128 + f] = Wv[i];
        row[192 + f] = Ws[i];
    }
    // Load x tile transposed: xst[kk][nl]
    for (int i = t; i < 4096; i += 256) {
        int nl = i >> 6, kk = i & 63;
        int n = n0g + nl;
        xst[kk * 68 + nl] = (n < NN) ? in[n * 64 + kk] : 0.f;
    }
    __syncthreads();

    const int l  = t & 31;
    const int wp = t >> 5;
    const int fA = l * 4;        // concat feats [0,128): q|k
    const int n0 = wp * 8;

    float acc[8][8];
#pragma unroll
    for (int i = 0; i < 8; i++)
#pragma unroll
        for (int j = 0; j < 8; j++) acc[i][j] = 0.f;

#pragma unroll 2
    for (int kk = 0; kk < 64; kk++) {
        const float* xr = &xst[kk * 68 + n0];
        float4 xa = *(const float4*)xr;
        float4 xb = *(const float4*)(xr + 4);
        const float* wr = &Wsh[kk * 256];
        float4 wa = *(const float4*)(wr + fA);          // q|k slice
        float4 wb = *(const float4*)(wr + 128 + fA);    // v|s slice
        float xv[8] = {xa.x, xa.y, xa.z, xa.w, xb.x, xb.y, xb.z, xb.w};
#pragma unroll
        for (int i = 0; i < 8; i++) {
            acc[i][0] += xv[i] * wa.x;
            acc[i][1] += xv[i] * wa.y;
            acc[i][2] += xv[i] * wa.z;
            acc[i][3] += xv[i] * wa.w;
            acc[i][4] += xv[i] * wb.x;
            acc[i][5] += xv[i] * wb.y;
            acc[i][6] += xv[i] * wb.z;
            acc[i][7] += xv[i] * wb.w;
        }
    }

    // Output routing: lanes 0-15 -> q & v, lanes 16-31 -> k & s
    const int fo = fA & 63;
    float* outA;  const float* bA;
    float* outB;  const float* bB;
    if (l < 16) { outA = g_q; bA = bq; outB = g_v; bB = bv; }
    else        { outA = g_k; bA = bk; outB = g_s; bB = bs; }
    float4 biasA = *(const float4*)&bA[fo];
    float4 biasB = *(const float4*)&bB[fo];

#pragma unroll
    for (int i = 0; i < 8; i++) {
        int n = n0g + n0 + i;
        if (n < NN) {
            float4 rA, rB;
            rA.x = acc[i][0] + biasA.x; rA.y = acc[i][1] + biasA.y;
            rA.z = acc[i][2] + biasA.z; rA.w = acc[i][3] + biasA.w;
            rB.x = acc[i][4] + biasB.x; rB.y = acc[i][5] + biasB.y;
            rB.z = acc[i][6] + biasB.z; rB.w = acc[i][7] + biasB.w;
            *(float4*)&outA[n * 64 + fo] = rA;
            *(float4*)&outB[n * 64 + fo] = rB;
        }
    }
}

// ---------------- edge aggregation: warp per dst, online softmax, 2-way ILP -
__device__ __forceinline__ void edge_step(int i, float qx, float qy,
                                          float wex, float wey, int lane2,
                                          float& m, float& s, float& a0, float& a1) {
    int   src = g_csrc[i];
    float w   = g_cw[i];
    float e0 = w * wex, e1 = w * wey;
    const float2 kk = *(const float2*)&g_k[src * 64 + lane2];
    const float2 vv = *(const float2*)&g_v[src * 64 + lane2];
    float k0 = kk.x + e0, k1 = kk.y + e1;
    float v0 = vv.x + e0, v1 = vv.y + e1;

    float p = qx * k0 + qy * k1;
#pragma unroll
    for (int off = 16; off; off >>= 1)
        p += __shfl_xor_sync(0xffffffffu, p, off);
    float logit = p * 0.125f;  // 1/sqrt(64)

    float nm = fmaxf(m, logit);
    float sc = __expf(m - nm);
    float pe = __expf(logit - nm);
    s  = s * sc + pe;
    a0 = a0 * sc + pe * v0;
    a1 = a1 * sc + pe * v1;
    m  = nm;
}

__global__ __launch_bounds__(256) void edge_agg_kernel(
    const float* __restrict__ We, int do_pool, const int* __restrict__ batch) {
    int wid  = (blockIdx.x * blockDim.x + threadIdx.x) >> 5;
    int lane = threadIdx.x & 31;
    if (wid >= NN) return;
    const int dst = wid;
    const int lane2 = lane * 2;

    const int i0 = g_off[dst], i1 = g_off[dst + 1];
    const float2 qv = *(const float2*)&g_q[dst * 64 + lane2];
    const float2 we = *(const float2*)&We[lane2];

    float m0 = -1e30f, s0 = 0.f, p00 = 0.f, p01 = 0.f;
    float m1 = -1e30f, s1 = 0.f, p10 = 0.f, p11 = 0.f;

    int i = i0;
    for (; i + 1 < i1; i += 2) {
        edge_step(i,     qv.x, qv.y, we.x, we.y, lane2, m0, s0, p00, p01);
        edge_step(i + 1, qv.x, qv.y, we.x, we.y, lane2, m1, s1, p10, p11);
    }
    if (i < i1)
        edge_step(i, qv.x, qv.y, we.x, we.y, lane2, m0, s0, p00, p01);

    // merge the two online accumulators
    float nm = fmaxf(m0, m1);
    float c0 = __expf(m0 - nm), c1 = __expf(m1 - nm);
    float s  = s0 * c0 + s1 * c1;
    float a0 = p00 * c0 + p10 * c1;
    float a1 = p01 * c0 + p11 * c1;

    float inv = 1.f / (s + 1e-16f);
    const float2 sk = *(const float2*)&g_s[dst * 64 + lane2];
    float2 o;
    o.x = fmaxf(a0 * inv + sk.x, 0.f);
    o.y = fmaxf(a1 * inv + sk.y, 0.f);

    if (do_pool) {
        int g = batch[dst];
        atomicAdd(&g_pool[g * 64 + lane2],     o.x);
        atomicAdd(&g_pool[g * 64 + lane2 + 1], o.y);
    } else {
        *(float2*)&g_h[dst * 64 + lane2] = o;
    }
}

// ---------------- classifier head ------------------------------------------
__global__ void final_kernel(const float* __restrict__ Wl,
                             const float* __restrict__ bl,
                             float* __restrict__ out) {
    int t = threadIdx.x;  // 512 = GG * 2
    int g = t >> 1, c = t & 1;
    float cnt = fmaxf(g_pcnt[g], 1.f);
    float sum = 0.f;
    for (int f = 0; f < 64; f++)
        sum += g_pool[g * 64 + f] * Wl[f * 2 + c];
    out[g * 2 + c] = sum / cnt + bl[c];
}

// ---------------- launch ----------------------------------------------------
extern "C" void kernel_launch(void* const* d_in, const int* in_sizes, int n_in,
                              void* d_out, int out_size) {
    const float* x     = (const float*)d_in[0];
    const int*   ei    = (const int*)d_in[1];
    const float* ew    = (const float*)d_in[2];
    const int*   batch = (const int*)d_in[3];
    const float *Wq1 = (const float*)d_in[4],  *bq1 = (const float*)d_in[5];
    const float *Wk1 = (const float*)d_in[6],  *bk1 = (const float*)d_in[7];
    const float *Wv1 = (const float*)d_in[8],  *bv1 = (const float*)d_in[9];
    const float *We1 = (const float*)d_in[10];
    const float *Ws1 = (const float*)d_in[11], *bs1 = (const float*)d_in[12];
    const float *Wq2 = (const float*)d_in[13], *bq2 = (const float*)d_in[14];
    const float *Wk2 = (const float*)d_in[15], *bk2 = (const float*)d_in[16];
    const float *Wv2 = (const float*)d_in[17], *bv2 = (const float*)d_in[18];
    const float *We2 = (const float*)d_in[19];
    const float *Ws2 = (const float*)d_in[20], *bs2 = (const float*)d_in[21];
    const float *Wl  = (const float*)d_in[22], *bl  = (const float*)d_in[23];
    float* out = (float*)d_out;

    cudaFuncSetAttribute(gemm4_kernel,
                         cudaFuncAttributeMaxDynamicSharedMemorySize, GEMM_SMEM);

    const int GEMM_BLOCKS  = (NN + 63) / 64;                     // 782
    const int COUNT_BLOCKS = (EE / 4 + NN / 4 + 255) / 256;      // 831
    const int SCAT_BLOCKS  = (EE / 4 + 255) / 256;               // 782
    const int WARP_BLOCKS  = (NN * 32 + 255) / 256;              // 6250

    // CSR build (shared by both layers) + scratch zeroing
    zero_kernel<<<469, 256>>>();
    count_kernel<<<COUNT_BLOCKS, 256>>>(ei, batch);
    scan_kernel<<<1, SCAN_T>>>();
    scatter_kernel<<<SCAT_BLOCKS, 256>>>(ei, ew);

    // Layer 1
    gemm4_kernel<<<GEMM_BLOCKS, 256, GEMM_SMEM>>>(x, 0, Wq1, bq1, Wk1, bk1,
                                                  Wv1, bv1, Ws1, bs1);
    edge_agg_kernel<<<WARP_BLOCKS, 256>>>(We1, 0, batch);

    // Layer 2 (input = g_h; pooling fused, h never materialized)
    gemm4_kernel<<<GEMM_BLOCKS, 256, GEMM_SMEM>>>(x, 1, Wq2, bq2, Wk2, bk2,
                                                  Wv2, bv2, Ws2, bs2);
    edge_agg_kernel<<<WARP_BLOCKS, 256>>>(We2, 1, batch);

    // Head
    final_kernel<<<1, 512>>>(Wl, bl, out);
}